// round 13
// baseline (speedup 1.0000x reference)
#include <cuda_runtime.h>

#define BATCH 4
#define CDIM 192
#define HH 192
#define WWd 192
#define HW (HH * WWd)            // 36864 pixels per batch image
#define WS 16
#define NHEADS 6
#define HD 32
#define NTOK 256                 // WS*WS
#define HDIV 12
#define WDIV 12
#define WIN_PER_B (HDIV * WDIV)  // 144
#define NWIN (BATCH * WIN_PER_B) // 576
#define RPE ((2 * WS - 1) * (2 * WS - 1)) // 961
#define SCALE 0.17677669529663687f        // 1/sqrt(32)

#define WIN_ELEMS (NWIN * NHEADS * NTOK * HD) // 28,311,552 floats

// Scratch (allocation-free rule: __device__ globals)
__device__ float g_q[WIN_ELEMS];
__device__ float g_k[WIN_ELEMS];
__device__ float g_v[WIN_ELEMS];
__device__ float g_att[BATCH * CDIM * HW]; // attention result, BCHW

// ---------------------------------------------------------------------------
// helpers
// ---------------------------------------------------------------------------
__device__ __forceinline__ unsigned tf32r(float x) {
    unsigned r;
    asm("cvt.rna.tf32.f32 %0, %1;" : "=r"(r) : "f"(x));
    return r;
}

__device__ __forceinline__ void mma8(float4& c,
                                     unsigned a0, unsigned a1, unsigned a2, unsigned a3,
                                     unsigned b0, unsigned b1) {
    asm("mma.sync.aligned.m16n8k8.row.col.f32.tf32.tf32.f32 "
        "{%0,%1,%2,%3},{%4,%5,%6,%7},{%8,%9},{%0,%1,%2,%3};"
        : "+f"(c.x), "+f"(c.y), "+f"(c.z), "+f"(c.w)
        : "r"(a0), "r"(a1), "r"(a2), "r"(a3), "r"(b0), "r"(b1));
}

__device__ __forceinline__ void cp16(float* dst_smem, const float* src) {
    unsigned s = (unsigned)__cvta_generic_to_shared(dst_smem);
    asm volatile("cp.async.cg.shared.global [%0], [%1], 16;\n" :: "r"(s), "l"(src));
}

// ---------------------------------------------------------------------------
// 1x1 conv as TF32 tensor-core GEMM, 4-stage cp.async pipeline for B;
// A (weights) fragments loaded directly from gmem (L1/L2-resident, 147KB).
// Block tile: 64 out x 256 px, 8 warps in 2(M) x 4(N), 2x8 m16n8k8 frags.
// One __syncthreads per k-chunk; empty commit_group padding keeps
// wait_group 2 valid in the tail (FIFO completion).
// ---------------------------------------------------------------------------
#define BLD 264
#define NSTAGE 4
#define BSTG (16 * BLD)
#define NITER (CDIM / 16)   // 12
#define CONV_DSMEM (NSTAGE * BSTG * 4)  // 67584 bytes

template <int MODE>
__global__ __launch_bounds__(256, 2)
void conv1x1_mma(const float* __restrict__ xin,
                 const float* __restrict__ w,
                 const float* __restrict__ bias,
                 float* __restrict__ outp) {
    extern __shared__ float Bs[];   // [NSTAGE][16][BLD] raw fp32

    const int tid  = threadIdx.x;
    const int b    = blockIdx.z;
    const int p0   = blockIdx.x * 256;
    const int o0   = blockIdx.y * 64;
    const int lane = tid & 31;
    const int warp = tid >> 5;
    const int wm   = warp >> 2;
    const int wn   = warp & 3;
    const int gid  = lane >> 2;
    const int tig  = lane & 3;
    const int m0   = wm * 32;
    const int n0   = wn * 64;

    const float* src = (MODE == 2) ? g_att : xin;
    const float* xb  = src + (size_t)b * CDIM * HW;

    const int bkk = tid >> 6;          // 0..3
    const int bp4 = (tid & 63) * 4;

    float4 acc[2][8];
#pragma unroll
    for (int mf = 0; mf < 2; mf++)
#pragma unroll
        for (int nf = 0; nf < 8; nf++) acc[mf][nf] = make_float4(0.f, 0.f, 0.f, 0.f);

    auto fillB = [&](int st, int k0) {
#pragma unroll
        for (int r = 0; r < 4; r++) {
            int kk = bkk + r * 4;
            cp16(&Bs[st * BSTG + kk * BLD + bp4], &xb[(size_t)(k0 + kk) * HW + p0 + bp4]);
        }
    };

    fillB(0, 0);  asm volatile("cp.async.commit_group;\n");
    fillB(1, 16); asm volatile("cp.async.commit_group;\n");
    fillB(2, 32); asm volatile("cp.async.commit_group;\n");

    for (int it = 0; it < NITER; it++) {
        asm volatile("cp.async.wait_group 2;\n");   // chunk `it` fill complete
        __syncthreads();                            // visibility + all past it-1
        if (it + 3 < NITER) fillB((it + 3) & 3, (it + 3) * 16);
        asm volatile("cp.async.commit_group;\n");   // real or empty group

        const float* B = &Bs[(it & 3) * BSTG];
        const int k0 = it * 16;
#pragma unroll
        for (int ks = 0; ks < 16; ks += 8) {
            unsigned a[2][4];
#pragma unroll
            for (int mf = 0; mf < 2; mf++) {
                const float* wr = &w[(size_t)(o0 + m0 + mf * 16 + gid) * CDIM + k0 + ks];
                a[mf][0] = tf32r(__ldg(wr + tig));
                a[mf][1] = tf32r(__ldg(wr + 8 * CDIM + tig));
                a[mf][2] = tf32r(__ldg(wr + tig + 4));
                a[mf][3] = tf32r(__ldg(wr + 8 * CDIM + tig + 4));
            }
            unsigned bb[8][2];
#pragma unroll
            for (int nf = 0; nf < 8; nf++) {
                int nc = n0 + nf * 8 + gid;
                bb[nf][0] = tf32r(B[(ks + tig) * BLD + nc]);
                bb[nf][1] = tf32r(B[(ks + tig + 4) * BLD + nc]);
            }
#pragma unroll
            for (int mf = 0; mf < 2; mf++)
#pragma unroll
                for (int nf = 0; nf < 8; nf++)
                    mma8(acc[mf][nf], a[mf][0], a[mf][1], a[mf][2], a[mf][3],
                         bb[nf][0], bb[nf][1]);
        }
    }

    // ---- epilogue (validated R6-R10; unchanged) ----
#pragma unroll
    for (int mf = 0; mf < 2; mf++) {
        const int o   = o0 + m0 + mf * 16 + gid;
        const float bo0 = bias[o];
        const float bo8 = bias[o + 8];
        if (MODE == 2) {
#pragma unroll
            for (int nf = 0; nf < 8; nf++) {
                int p = p0 + n0 + nf * 8 + 2 * tig;
                float2 v0 = make_float2(acc[mf][nf].x + bo0, acc[mf][nf].y + bo0);
                float2 v8 = make_float2(acc[mf][nf].z + bo8, acc[mf][nf].w + bo8);
                *(float2*)&outp[((size_t)b * CDIM + o) * HW + p]     = v0;
                *(float2*)&outp[((size_t)b * CDIM + o + 8) * HW + p] = v8;
            }
        } else {
            const int head = (MODE == 0) ? (o >> 5)
                           : ((o < CDIM) ? (o >> 5) : ((o - CDIM) >> 5));
            const int c0ch = (MODE == 0) ? (o & 31)
                           : ((o < CDIM) ? (o & 31) : ((o - CDIM) & 31));
            float* g = (MODE == 0) ? g_q : ((o < CDIM) ? g_k : g_v);
#pragma unroll
            for (int nf = 0; nf < 8; nf++) {
                int p = p0 + n0 + nf * 8 + 2 * tig;
                int y = p / WWd;
                int x = p - y * WWd;
                int win = b * WIN_PER_B + (y >> 4) * WDIV + (x >> 4);
                int n   = ((y & 15) << 4) + (x & 15);
                size_t base = (((size_t)win * NHEADS + head) * NTOK + n) * HD + c0ch;
                g[base]          = acc[mf][nf].x + bo0;
                g[base + 32]     = acc[mf][nf].y + bo0;
                g[base + 8]      = acc[mf][nf].z + bo8;
                g[base + 40]     = acc[mf][nf].w + bo8;
            }
        }
    }
}

// ---------------------------------------------------------------------------
// TF32 tensor-core windowed attention with double-buffered K/V staging:
// LDG for chunk it+1 issued before computing chunk it (latency hidden),
// cvt+STS into the alternate buffer, ONE __syncthreads per chunk.
// Compute core (S/P/PV/softmax/epilogue) unchanged from validated R7.
// ---------------------------------------------------------------------------
#define KLD 36
#define VLD 40
#define OLD 33
#define BUFW (32 * KLD + 32 * VLD)   // 2432 words per buffer set

__global__ __launch_bounds__(256)
void attn_mma(const float* __restrict__ rpb) {
    __shared__ float sm[NTOK * OLD];         // 8448 floats; unioned usage
    // [buf0 K][buf0 V][buf1 K][buf1 V][bias]; osh reuses everything
    float* bsh = sm + 2 * BUFW;              // [961]
    float* osh = sm;

    const int tid  = threadIdx.x;
    const int lane = tid & 31;
    const int warp = tid >> 5;
    const int gid  = lane >> 2;
    const int tig  = lane & 3;
    const int m0   = warp * 32;

    const int win  = blockIdx.x / NHEADS;
    const int head = blockIdx.x % NHEADS;
    const size_t whbase = ((size_t)win * NHEADS + head) * NTOK;

    for (int i = tid; i < RPE; i += 256) bsh[i] = rpb[head * RPE + i];

    unsigned qa[2][4][4];
#pragma unroll
    for (int mf = 0; mf < 2; mf++) {
        const float* q0 = g_q + (whbase + m0 + mf * 16 + gid) * HD;
        const float* q1 = q0 + 8 * HD;
#pragma unroll
        for (int ks = 0; ks < 4; ks++) {
            qa[mf][ks][0] = tf32r(q0[ks * 8 + tig] * SCALE);
            qa[mf][ks][1] = tf32r(q1[ks * 8 + tig] * SCALE);
            qa[mf][ks][2] = tf32r(q0[ks * 8 + tig + 4] * SCALE);
            qa[mf][ks][3] = tf32r(q1[ks * 8 + tig + 4] * SCALE);
        }
    }

    float4 oacc[2][4];
#pragma unroll
    for (int mf = 0; mf < 2; mf++)
#pragma unroll
        for (int nf = 0; nf < 4; nf++) oacc[mf][nf] = make_float4(0.f, 0.f, 0.f, 0.f);
    float lsum[2][2] = {{0.f, 0.f}, {0.f, 0.f}};

    int ro[2][2];
#pragma unroll
    for (int mf = 0; mf < 2; mf++)
#pragma unroll
        for (int rr = 0; rr < 2; rr++) {
            int r = m0 + mf * 16 + gid + rr * 8;
            ro[mf][rr] = (15 - (r >> 4)) * 31 + (15 - (r & 15));
        }

    const int srow = tid >> 3;
    const int scol = (tid & 7) * 4;

    // stage chunk 0 into buffer 0
    {
        float4 kt = *(const float4*)(g_k + (whbase + srow) * HD + scol);
        float4 vt = *(const float4*)(g_v + (whbase + srow) * HD + scol);
        uint4 ku; ku.x = tf32r(kt.x); ku.y = tf32r(kt.y); ku.z = tf32r(kt.z); ku.w = tf32r(kt.w);
        uint4 vu; vu.x = tf32r(vt.x); vu.y = tf32r(vt.y); vu.z = tf32r(vt.z); vu.w = tf32r(vt.w);
        *(uint4*)((unsigned*)sm + srow * KLD + scol) = ku;
        *(uint4*)((unsigned*)sm + 32 * KLD + srow * VLD + scol) = vu;
    }
    __syncthreads();

    for (int it = 0; it < 8; it++) {
        const int cur = it & 1;
        const unsigned* kshu = (const unsigned*)sm + cur * BUFW;
        const unsigned* vshu = kshu + 32 * KLD;

        // prefetch chunk it+1 (gmem latency hidden behind compute)
        float4 kt, vt;
        if (it < 7) {
            kt = *(const float4*)(g_k + (whbase + (it + 1) * 32 + srow) * HD + scol);
            vt = *(const float4*)(g_v + (whbase + (it + 1) * 32 + srow) * HD + scol);
        }

        const int c0 = it * 32;

        float4 sacc[2][4];
#pragma unroll
        for (int mf = 0; mf < 2; mf++)
#pragma unroll
            for (int nf = 0; nf < 4; nf++) sacc[mf][nf] = make_float4(0.f, 0.f, 0.f, 0.f);
#pragma unroll
        for (int ks = 0; ks < 4; ks++)
#pragma unroll
            for (int nf = 0; nf < 4; nf++) {
                unsigned b0 = kshu[(nf * 8 + gid) * KLD + ks * 8 + tig];
                unsigned b1 = kshu[(nf * 8 + gid) * KLD + ks * 8 + tig + 4];
                mma8(sacc[0][nf], qa[0][ks][0], qa[0][ks][1], qa[0][ks][2], qa[0][ks][3], b0, b1);
                mma8(sacc[1][nf], qa[1][ks][0], qa[1][ks][1], qa[1][ks][2], qa[1][ks][3], b0, b1);
            }

#pragma unroll
        for (int mf = 0; mf < 2; mf++)
#pragma unroll
            for (int nf = 0; nf < 4; nf++) {
                int c  = c0 + nf * 8 + 2 * tig;
                int co = (c >> 4) * 31 + (c & 15);
                float4 s = sacc[mf][nf];
                float px = __expf(s.x + bsh[ro[mf][0] + co]);
                float py = __expf(s.y + bsh[ro[mf][0] + co + 1]);
                float pz = __expf(s.z + bsh[ro[mf][1] + co]);
                float pw = __expf(s.w + bsh[ro[mf][1] + co + 1]);
                lsum[mf][0] += px + py;
                lsum[mf][1] += pz + pw;
                sacc[mf][nf] = make_float4(px, py, pz, pw);
            }

#pragma unroll
        for (int mf = 0; mf < 2; mf++)
#pragma unroll
            for (int ks = 0; ks < 4; ks++) {
                float4 f = sacc[mf][ks];
                int s0 = (lane & 28) | (tig >> 1);
                float x0 = __shfl_sync(0xffffffffu, f.x, s0);
                float y0 = __shfl_sync(0xffffffffu, f.y, s0);
                float z0 = __shfl_sync(0xffffffffu, f.z, s0);
                float w0 = __shfl_sync(0xffffffffu, f.w, s0);
                float x1 = __shfl_sync(0xffffffffu, f.x, s0 + 2);
                float y1 = __shfl_sync(0xffffffffu, f.y, s0 + 2);
                float z1 = __shfl_sync(0xffffffffu, f.z, s0 + 2);
                float w1 = __shfl_sync(0xffffffffu, f.w, s0 + 2);
                bool odd = (tig & 1);
                unsigned a0 = tf32r(odd ? y0 : x0);
                unsigned a1 = tf32r(odd ? w0 : z0);
                unsigned a2 = tf32r(odd ? y1 : x1);
                unsigned a3 = tf32r(odd ? w1 : z1);
#pragma unroll
                for (int nf = 0; nf < 4; nf++) {
                    unsigned b0 = vshu[(ks * 8 + tig) * VLD + nf * 8 + gid];
                    unsigned b1 = vshu[(ks * 8 + tig + 4) * VLD + nf * 8 + gid];
                    mma8(oacc[mf][nf], a0, a1, a2, a3, b0, b1);
                }
            }

        // publish chunk it+1 into the alternate buffer
        if (it < 7) {
            unsigned* nk = (unsigned*)sm + (cur ^ 1) * BUFW;
            uint4 ku; ku.x = tf32r(kt.x); ku.y = tf32r(kt.y); ku.z = tf32r(kt.z); ku.w = tf32r(kt.w);
            uint4 vu; vu.x = tf32r(vt.x); vu.y = tf32r(vt.y); vu.z = tf32r(vt.z); vu.w = tf32r(vt.w);
            *(uint4*)(nk + srow * KLD + scol) = ku;
            *(uint4*)(nk + 32 * KLD + srow * VLD + scol) = vu;
        }
        __syncthreads();
    }

    float linv[2][2];
#pragma unroll
    for (int mf = 0; mf < 2; mf++)
#pragma unroll
        for (int rr = 0; rr < 2; rr++) {
            float l = lsum[mf][rr];
            l += __shfl_xor_sync(0xffffffffu, l, 1);
            l += __shfl_xor_sync(0xffffffffu, l, 2);
            linv[mf][rr] = 1.0f / l;
        }

#pragma unroll
    for (int mf = 0; mf < 2; mf++)
#pragma unroll
        for (int nf = 0; nf < 4; nf++) {
            float4 o = oacc[mf][nf];
            int r0 = m0 + mf * 16 + gid;
            int d  = nf * 8 + 2 * tig;
            osh[r0 * OLD + d]           = o.x * linv[mf][0];
            osh[r0 * OLD + d + 1]       = o.y * linv[mf][0];
            osh[(r0 + 8) * OLD + d]     = o.z * linv[mf][1];
            osh[(r0 + 8) * OLD + d + 1] = o.w * linv[mf][1];
        }
    __syncthreads();

    const int b    = win / WIN_PER_B;
    const int wrem = win % WIN_PER_B;
    const int py   = (wrem / WDIV) * WS + (tid >> 4);
    const int px   = (wrem % WDIV) * WS + (tid & 15);
    float* gbase = g_att + ((size_t)b * CDIM + head * HD) * HW + (size_t)py * WWd + px;
#pragma unroll
    for (int d = 0; d < HD; d++)
        gbase[(size_t)d * HW] = osh[tid * OLD + d];
}

// ---------------------------------------------------------------------------
extern "C" void kernel_launch(void* const* d_in, const int* in_sizes, int n_in,
                              void* d_out, int out_size) {
    const float* x     = (const float*)d_in[0];
    const float* ref   = (const float*)d_in[1];
    const float* w_q   = (const float*)d_in[2];
    const float* b_q   = (const float*)d_in[3];
    const float* w_kv  = (const float*)d_in[4];
    const float* b_kv  = (const float*)d_in[5];
    const float* w_out = (const float*)d_in[6];
    const float* b_out = (const float*)d_in[7];
    const float* rpb   = (const float*)d_in[8];
    float* out = (float*)d_out;

    // >48KB dynamic smem: set attribute every call (idempotent, no statics)
    cudaFuncSetAttribute(conv1x1_mma<0>, cudaFuncAttributeMaxDynamicSharedMemorySize, CONV_DSMEM);
    cudaFuncSetAttribute(conv1x1_mma<1>, cudaFuncAttributeMaxDynamicSharedMemorySize, CONV_DSMEM);
    cudaFuncSetAttribute(conv1x1_mma<2>, cudaFuncAttributeMaxDynamicSharedMemorySize, CONV_DSMEM);

    dim3 blk(256);
    conv1x1_mma<0><<<dim3(HW / 256, CDIM / 64, BATCH), blk, CONV_DSMEM>>>(x, w_q, b_q, nullptr);
    conv1x1_mma<1><<<dim3(HW / 256, (2 * CDIM) / 64, BATCH), blk, CONV_DSMEM>>>(ref, w_kv, b_kv, nullptr);
    attn_mma<<<NWIN * NHEADS, blk>>>(rpb);
    conv1x1_mma<2><<<dim3(HW / 256, CDIM / 64, BATCH), blk, CONV_DSMEM>>>(nullptr, w_out, b_out, out);
}

// round 15
// speedup vs baseline: 1.2932x; 1.2932x over previous
#include <cuda_runtime.h>

#define BATCH 4
#define CDIM 192
#define HH 192
#define WWd 192
#define HW (HH * WWd)            // 36864 pixels per batch image
#define WS 16
#define NHEADS 6
#define HD 32
#define NTOK 256                 // WS*WS
#define HDIV 12
#define WDIV 12
#define WIN_PER_B (HDIV * WDIV)  // 144
#define NWIN (BATCH * WIN_PER_B) // 576
#define RPE ((2 * WS - 1) * (2 * WS - 1)) // 961
#define SCALE 0.17677669529663687f        // 1/sqrt(32)

#define WIN_ELEMS (NWIN * NHEADS * NTOK * HD) // 28,311,552 floats

// Scratch (allocation-free rule: __device__ globals)
__device__ float g_q[WIN_ELEMS];
__device__ float g_k[WIN_ELEMS];
__device__ float g_v[WIN_ELEMS];
__device__ float g_att[BATCH * CDIM * HW]; // attention result, BCHW

// ---------------------------------------------------------------------------
// helpers
// ---------------------------------------------------------------------------
__device__ __forceinline__ unsigned tf32r(float x) {
    unsigned r;
    asm("cvt.rna.tf32.f32 %0, %1;" : "=r"(r) : "f"(x));
    return r;
}

__device__ __forceinline__ void mma8(float4& c,
                                     unsigned a0, unsigned a1, unsigned a2, unsigned a3,
                                     unsigned b0, unsigned b1) {
    asm("mma.sync.aligned.m16n8k8.row.col.f32.tf32.tf32.f32 "
        "{%0,%1,%2,%3},{%4,%5,%6,%7},{%8,%9},{%0,%1,%2,%3};"
        : "+f"(c.x), "+f"(c.y), "+f"(c.z), "+f"(c.w)
        : "r"(a0), "r"(a1), "r"(a2), "r"(a3), "r"(b0), "r"(b1));
}

__device__ __forceinline__ void cp16(float* dst_smem, const float* src) {
    unsigned s = (unsigned)__cvta_generic_to_shared(dst_smem);
    asm volatile("cp.async.cg.shared.global [%0], [%1], 16;\n" :: "r"(s), "l"(src));
}

// ---------------------------------------------------------------------------
// 1x1 conv as TF32 tensor-core GEMM. R10-validated structure (A AND B tiles
// staged in smem via cp.async, conflict-free strides 20/264, tf32 cvt at
// consume) with the ring deepened 2 -> 3 stages (prefetch distance 2).
// Group algebra: 2 fills pre-committed; at iter `it` wait_group 1 => chunk
// `it` complete (FIFO); barrier retires reads of stage (it+2)%3; refill it.
// 66KB dynamic smem, 2 CTAs/SM (132KB < 228KB carveout).
// ---------------------------------------------------------------------------
#define ALD 20
#define BLD 264
#define ASZ (64 * ALD)           // 1280 floats
#define BSZ (16 * BLD)           // 4224 floats
#define STG (ASZ + BSZ)          // 5504 floats per stage
#define NSTAGE 3
#define NITER (CDIM / 16)        // 12
#define CONV_DSMEM (NSTAGE * STG * 4)  // 66048 bytes

template <int MODE>
__global__ __launch_bounds__(256, 2)
void conv1x1_mma(const float* __restrict__ xin,
                 const float* __restrict__ w,
                 const float* __restrict__ bias,
                 float* __restrict__ outp) {
    extern __shared__ float S[];   // [NSTAGE][A | B] raw fp32

    const int tid  = threadIdx.x;
    const int b    = blockIdx.z;
    const int p0   = blockIdx.x * 256;
    const int o0   = blockIdx.y * 64;
    const int lane = tid & 31;
    const int warp = tid >> 5;
    const int wm   = warp >> 2;
    const int wn   = warp & 3;
    const int gid  = lane >> 2;
    const int tig  = lane & 3;
    const int m0   = wm * 32;
    const int n0   = wn * 64;

    const float* src = (MODE == 2) ? g_att : xin;
    const float* xb  = src + (size_t)b * CDIM * HW;

    // fill indices (R10-validated)
    const int aoo = tid >> 2;          // 0..63
    const int akg = (tid & 3) * 4;     // k-group offset 0,4,8,12
    const int bkk = tid >> 6;          // 0..3
    const int bp4 = (tid & 63) * 4;    // pixel offset

    float4 acc[2][8];
#pragma unroll
    for (int mf = 0; mf < 2; mf++)
#pragma unroll
        for (int nf = 0; nf < 8; nf++) acc[mf][nf] = make_float4(0.f, 0.f, 0.f, 0.f);

    auto fill = [&](int st, int k0) {
        cp16(&S[st * STG + aoo * ALD + akg], &w[(size_t)(o0 + aoo) * CDIM + k0 + akg]);
#pragma unroll
        for (int r = 0; r < 4; r++) {
            int kk = bkk + r * 4;
            cp16(&S[st * STG + ASZ + kk * BLD + bp4],
                 &xb[(size_t)(k0 + kk) * HW + p0 + bp4]);
        }
    };

    fill(0, 0);  asm volatile("cp.async.commit_group;\n");
    fill(1, 16); asm volatile("cp.async.commit_group;\n");

    for (int it = 0; it < NITER; it++) {
        asm volatile("cp.async.wait_group 1;\n");   // chunk `it` fill complete
        __syncthreads();                            // retire reads of stage (it+2)%3
        if (it + 2 < NITER) fill((it + 2) % 3, (it + 2) * 16);
        asm volatile("cp.async.commit_group;\n");   // real or empty group

        const float* A = &S[(it % 3) * STG];
        const float* B = A + ASZ;
#pragma unroll
        for (int ks = 0; ks < 16; ks += 8) {
            unsigned a[2][4];
#pragma unroll
            for (int mf = 0; mf < 2; mf++) {
                int mrow = m0 + mf * 16 + gid;
                a[mf][0] = tf32r(A[mrow * ALD + ks + tig]);
                a[mf][1] = tf32r(A[(mrow + 8) * ALD + ks + tig]);
                a[mf][2] = tf32r(A[mrow * ALD + ks + tig + 4]);
                a[mf][3] = tf32r(A[(mrow + 8) * ALD + ks + tig + 4]);
            }
            unsigned bb[8][2];
#pragma unroll
            for (int nf = 0; nf < 8; nf++) {
                int nc = n0 + nf * 8 + gid;
                bb[nf][0] = tf32r(B[(ks + tig) * BLD + nc]);
                bb[nf][1] = tf32r(B[(ks + tig + 4) * BLD + nc]);
            }
#pragma unroll
            for (int mf = 0; mf < 2; mf++)
#pragma unroll
                for (int nf = 0; nf < 8; nf++)
                    mma8(acc[mf][nf], a[mf][0], a[mf][1], a[mf][2], a[mf][3],
                         bb[nf][0], bb[nf][1]);
        }
    }

    // ---- epilogue (validated R6-R13; unchanged) ----
#pragma unroll
    for (int mf = 0; mf < 2; mf++) {
        const int o   = o0 + m0 + mf * 16 + gid;
        const float bo0 = bias[o];
        const float bo8 = bias[o + 8];
        if (MODE == 2) {
#pragma unroll
            for (int nf = 0; nf < 8; nf++) {
                int p = p0 + n0 + nf * 8 + 2 * tig;
                float2 v0 = make_float2(acc[mf][nf].x + bo0, acc[mf][nf].y + bo0);
                float2 v8 = make_float2(acc[mf][nf].z + bo8, acc[mf][nf].w + bo8);
                *(float2*)&outp[((size_t)b * CDIM + o) * HW + p]     = v0;
                *(float2*)&outp[((size_t)b * CDIM + o + 8) * HW + p] = v8;
            }
        } else {
            const int head = (MODE == 0) ? (o >> 5)
                           : ((o < CDIM) ? (o >> 5) : ((o - CDIM) >> 5));
            const int c0ch = (MODE == 0) ? (o & 31)
                           : ((o < CDIM) ? (o & 31) : ((o - CDIM) & 31));
            float* g = (MODE == 0) ? g_q : ((o < CDIM) ? g_k : g_v);
#pragma unroll
            for (int nf = 0; nf < 8; nf++) {
                int p = p0 + n0 + nf * 8 + 2 * tig;
                int y = p / WWd;
                int x = p - y * WWd;
                int win = b * WIN_PER_B + (y >> 4) * WDIV + (x >> 4);
                int n   = ((y & 15) << 4) + (x & 15);
                size_t base = (((size_t)win * NHEADS + head) * NTOK + n) * HD + c0ch;
                g[base]          = acc[mf][nf].x + bo0;
                g[base + 32]     = acc[mf][nf].y + bo0;
                g[base + 8]      = acc[mf][nf].z + bo8;
                g[base + 40]     = acc[mf][nf].w + bo8;
            }
        }
    }
}

// ---------------------------------------------------------------------------
// TF32 tensor-core windowed attention — exact R7/R10 validated version
// (the R11 double-buffer variant regressed; reverted).
// ---------------------------------------------------------------------------
#define KLD 36
#define VLD 40
#define OLD 33

__global__ __launch_bounds__(256)
void attn_mma(const float* __restrict__ rpb) {
    __shared__ float sm[NTOK * OLD];        // 8448 floats; unioned usage
    unsigned* kshu = (unsigned*)sm;          // [32][KLD]
    unsigned* vshu = (unsigned*)sm + 32 * KLD; // [32][VLD]
    float* bsh = sm + 32 * KLD + 32 * VLD;   // [961]
    float* osh = sm;                         // [256][OLD] (after compute)

    const int tid  = threadIdx.x;
    const int lane = tid & 31;
    const int warp = tid >> 5;
    const int gid  = lane >> 2;
    const int tig  = lane & 3;
    const int m0   = warp * 32;

    const int win  = blockIdx.x / NHEADS;
    const int head = blockIdx.x % NHEADS;
    const size_t whbase = ((size_t)win * NHEADS + head) * NTOK;

    for (int i = tid; i < RPE; i += 256) bsh[i] = rpb[head * RPE + i];

    unsigned qa[2][4][4];
#pragma unroll
    for (int mf = 0; mf < 2; mf++) {
        const float* q0 = g_q + (whbase + m0 + mf * 16 + gid) * HD;
        const float* q1 = q0 + 8 * HD;
#pragma unroll
        for (int ks = 0; ks < 4; ks++) {
            qa[mf][ks][0] = tf32r(q0[ks * 8 + tig] * SCALE);
            qa[mf][ks][1] = tf32r(q1[ks * 8 + tig] * SCALE);
            qa[mf][ks][2] = tf32r(q0[ks * 8 + tig + 4] * SCALE);
            qa[mf][ks][3] = tf32r(q1[ks * 8 + tig + 4] * SCALE);
        }
    }

    float4 oacc[2][4];
#pragma unroll
    for (int mf = 0; mf < 2; mf++)
#pragma unroll
        for (int nf = 0; nf < 4; nf++) oacc[mf][nf] = make_float4(0.f, 0.f, 0.f, 0.f);
    float lsum[2][2] = {{0.f, 0.f}, {0.f, 0.f}};

    int ro[2][2];
#pragma unroll
    for (int mf = 0; mf < 2; mf++)
#pragma unroll
        for (int rr = 0; rr < 2; rr++) {
            int r = m0 + mf * 16 + gid + rr * 8;
            ro[mf][rr] = (15 - (r >> 4)) * 31 + (15 - (r & 15));
        }

    const int srow = tid >> 3;
    const int scol = (tid & 7) * 4;

    for (int c0 = 0; c0 < NTOK; c0 += 32) {
        __syncthreads();
        {
            float4 kt = *(const float4*)(g_k + (whbase + c0 + srow) * HD + scol);
            uint4 ku; ku.x = tf32r(kt.x); ku.y = tf32r(kt.y); ku.z = tf32r(kt.z); ku.w = tf32r(kt.w);
            *(uint4*)(kshu + srow * KLD + scol) = ku;
            float4 vt = *(const float4*)(g_v + (whbase + c0 + srow) * HD + scol);
            uint4 vu; vu.x = tf32r(vt.x); vu.y = tf32r(vt.y); vu.z = tf32r(vt.z); vu.w = tf32r(vt.w);
            *(uint4*)(vshu + srow * VLD + scol) = vu;
        }
        __syncthreads();

        float4 sacc[2][4];
#pragma unroll
        for (int mf = 0; mf < 2; mf++)
#pragma unroll
            for (int nf = 0; nf < 4; nf++) sacc[mf][nf] = make_float4(0.f, 0.f, 0.f, 0.f);
#pragma unroll
        for (int ks = 0; ks < 4; ks++)
#pragma unroll
            for (int nf = 0; nf < 4; nf++) {
                unsigned b0 = kshu[(nf * 8 + gid) * KLD + ks * 8 + tig];
                unsigned b1 = kshu[(nf * 8 + gid) * KLD + ks * 8 + tig + 4];
                mma8(sacc[0][nf], qa[0][ks][0], qa[0][ks][1], qa[0][ks][2], qa[0][ks][3], b0, b1);
                mma8(sacc[1][nf], qa[1][ks][0], qa[1][ks][1], qa[1][ks][2], qa[1][ks][3], b0, b1);
            }

#pragma unroll
        for (int mf = 0; mf < 2; mf++)
#pragma unroll
            for (int nf = 0; nf < 4; nf++) {
                int c  = c0 + nf * 8 + 2 * tig;
                int co = (c >> 4) * 31 + (c & 15);
                float4 s = sacc[mf][nf];
                float px = __expf(s.x + bsh[ro[mf][0] + co]);
                float py = __expf(s.y + bsh[ro[mf][0] + co + 1]);
                float pz = __expf(s.z + bsh[ro[mf][1] + co]);
                float pw = __expf(s.w + bsh[ro[mf][1] + co + 1]);
                lsum[mf][0] += px + py;
                lsum[mf][1] += pz + pw;
                sacc[mf][nf] = make_float4(px, py, pz, pw);
            }

#pragma unroll
        for (int mf = 0; mf < 2; mf++)
#pragma unroll
            for (int ks = 0; ks < 4; ks++) {
                float4 f = sacc[mf][ks];
                int s0 = (lane & 28) | (tig >> 1);
                float x0 = __shfl_sync(0xffffffffu, f.x, s0);
                float y0 = __shfl_sync(0xffffffffu, f.y, s0);
                float z0 = __shfl_sync(0xffffffffu, f.z, s0);
                float w0 = __shfl_sync(0xffffffffu, f.w, s0);
                float x1 = __shfl_sync(0xffffffffu, f.x, s0 + 2);
                float y1 = __shfl_sync(0xffffffffu, f.y, s0 + 2);
                float z1 = __shfl_sync(0xffffffffu, f.z, s0 + 2);
                float w1 = __shfl_sync(0xffffffffu, f.w, s0 + 2);
                bool odd = (tig & 1);
                unsigned a0 = tf32r(odd ? y0 : x0);
                unsigned a1 = tf32r(odd ? w0 : z0);
                unsigned a2 = tf32r(odd ? y1 : x1);
                unsigned a3 = tf32r(odd ? w1 : z1);
#pragma unroll
                for (int nf = 0; nf < 4; nf++) {
                    unsigned b0 = vshu[(ks * 8 + tig) * VLD + nf * 8 + gid];
                    unsigned b1 = vshu[(ks * 8 + tig + 4) * VLD + nf * 8 + gid];
                    mma8(oacc[mf][nf], a0, a1, a2, a3, b0, b1);
                }
            }
    }

    float linv[2][2];
#pragma unroll
    for (int mf = 0; mf < 2; mf++)
#pragma unroll
        for (int rr = 0; rr < 2; rr++) {
            float l = lsum[mf][rr];
            l += __shfl_xor_sync(0xffffffffu, l, 1);
            l += __shfl_xor_sync(0xffffffffu, l, 2);
            linv[mf][rr] = 1.0f / l;
        }

    __syncthreads();
#pragma unroll
    for (int mf = 0; mf < 2; mf++)
#pragma unroll
        for (int nf = 0; nf < 4; nf++) {
            float4 o = oacc[mf][nf];
            int r0 = m0 + mf * 16 + gid;
            int d  = nf * 8 + 2 * tig;
            osh[r0 * OLD + d]           = o.x * linv[mf][0];
            osh[r0 * OLD + d + 1]       = o.y * linv[mf][0];
            osh[(r0 + 8) * OLD + d]     = o.z * linv[mf][1];
            osh[(r0 + 8) * OLD + d + 1] = o.w * linv[mf][1];
        }
    __syncthreads();

    const int b    = win / WIN_PER_B;
    const int wrem = win % WIN_PER_B;
    const int py   = (wrem / WDIV) * WS + (tid >> 4);
    const int px   = (wrem % WDIV) * WS + (tid & 15);
    float* gbase = g_att + ((size_t)b * CDIM + head * HD) * HW + (size_t)py * WWd + px;
#pragma unroll
    for (int d = 0; d < HD; d++)
        gbase[(size_t)d * HW] = osh[tid * OLD + d];
}

// ---------------------------------------------------------------------------
extern "C" void kernel_launch(void* const* d_in, const int* in_sizes, int n_in,
                              void* d_out, int out_size) {
    const float* x     = (const float*)d_in[0];
    const float* ref   = (const float*)d_in[1];
    const float* w_q   = (const float*)d_in[2];
    const float* b_q   = (const float*)d_in[3];
    const float* w_kv  = (const float*)d_in[4];
    const float* b_kv  = (const float*)d_in[5];
    const float* w_out = (const float*)d_in[6];
    const float* b_out = (const float*)d_in[7];
    const float* rpb   = (const float*)d_in[8];
    float* out = (float*)d_out;

    // >48KB dynamic smem: set attribute every call (idempotent, no statics)
    cudaFuncSetAttribute(conv1x1_mma<0>, cudaFuncAttributeMaxDynamicSharedMemorySize, CONV_DSMEM);
    cudaFuncSetAttribute(conv1x1_mma<1>, cudaFuncAttributeMaxDynamicSharedMemorySize, CONV_DSMEM);
    cudaFuncSetAttribute(conv1x1_mma<2>, cudaFuncAttributeMaxDynamicSharedMemorySize, CONV_DSMEM);

    dim3 blk(256);
    conv1x1_mma<0><<<dim3(HW / 256, CDIM / 64, BATCH), blk, CONV_DSMEM>>>(x, w_q, b_q, nullptr);
    conv1x1_mma<1><<<dim3(HW / 256, (2 * CDIM) / 64, BATCH), blk, CONV_DSMEM>>>(ref, w_kv, b_kv, nullptr);
    attn_mma<<<NWIN * NHEADS, blk>>>(rpb);
    conv1x1_mma<2><<<dim3(HW / 256, CDIM / 64, BATCH), blk, CONV_DSMEM>>>(nullptr, w_out, b_out, out);
}

// round 17
// speedup vs baseline: 1.3387x; 1.0352x over previous
#include <cuda_runtime.h>

#define BATCH 4
#define CDIM 192
#define HH 192
#define WWd 192
#define HW (HH * WWd)            // 36864 pixels per batch image
#define WS 16
#define NHEADS 6
#define HD 32
#define NTOK 256                 // WS*WS
#define HDIV 12
#define WDIV 12
#define WIN_PER_B (HDIV * WDIV)  // 144
#define NWIN (BATCH * WIN_PER_B) // 576
#define RPE ((2 * WS - 1) * (2 * WS - 1)) // 961
#define SCALE 0.17677669529663687f        // 1/sqrt(32)

#define WIN_ELEMS (NWIN * NHEADS * NTOK * HD) // 28,311,552 floats

// Scratch (allocation-free rule: __device__ globals)
__device__ float g_q[WIN_ELEMS];     // tf32-pre-rounded, SCALE folded
__device__ float g_k[WIN_ELEMS];     // tf32-pre-rounded
__device__ float g_v[WIN_ELEMS];     // tf32-pre-rounded
__device__ float g_att[BATCH * CDIM * HW]; // tf32-pre-rounded, BCHW
__device__ float g_wq[CDIM * CDIM];        // tf32-pre-rounded weights
__device__ float g_wkv[2 * CDIM * CDIM];
__device__ float g_wout[CDIM * CDIM];

// ---------------------------------------------------------------------------
// helpers
// ---------------------------------------------------------------------------
__device__ __forceinline__ unsigned tf32r(float x) {
    unsigned r;
    asm("cvt.rna.tf32.f32 %0, %1;" : "=r"(r) : "f"(x));
    return r;
}
__device__ __forceinline__ float rnd(float x) { return __uint_as_float(tf32r(x)); }

__device__ __forceinline__ void mma8(float4& c,
                                     unsigned a0, unsigned a1, unsigned a2, unsigned a3,
                                     unsigned b0, unsigned b1) {
    asm("mma.sync.aligned.m16n8k8.row.col.f32.tf32.tf32.f32 "
        "{%0,%1,%2,%3},{%4,%5,%6,%7},{%8,%9},{%0,%1,%2,%3};"
        : "+f"(c.x), "+f"(c.y), "+f"(c.z), "+f"(c.w)
        : "r"(a0), "r"(a1), "r"(a2), "r"(a3), "r"(b0), "r"(b1));
}

__device__ __forceinline__ void cp16(float* dst_smem, const float* src) {
    unsigned s = (unsigned)__cvta_generic_to_shared(dst_smem);
    asm volatile("cp.async.cg.shared.global [%0], [%1], 16;\n" :: "r"(s), "l"(src));
}

// ---------------------------------------------------------------------------
// prep: round weights to tf32 once (values then consumed bit-directly)
// ---------------------------------------------------------------------------
__global__ void round_weights(const float* __restrict__ wq,
                              const float* __restrict__ wkv,
                              const float* __restrict__ wout) {
    int i = blockIdx.x * 256 + threadIdx.x;   // grid covers 73728
    if (i < CDIM * CDIM)     g_wq[i]   = rnd(wq[i]);
    if (i < 2 * CDIM * CDIM) g_wkv[i]  = rnd(wkv[i]);
    if (i < CDIM * CDIM)     g_wout[i] = rnd(wout[i]);
}

// ---------------------------------------------------------------------------
// 1x1 conv as TF32 tensor-core GEMM, 3-stage cp.async ring (R15-validated).
// A operands: pre-rounded weights -> raw-bit consume (no cvt).
// B operands: MODE2 reads pre-rounded g_att -> raw-bit; MODE0/1 cvt at consume.
// MODE0/1 epilogues store tf32-pre-rounded q/k/v (SCALE folded into q).
// ---------------------------------------------------------------------------
#define ALD 20
#define BLD 264
#define ASZ (64 * ALD)
#define BSZ (16 * BLD)
#define STG (ASZ + BSZ)
#define NSTAGE 3
#define NITER (CDIM / 16)        // 12
#define CONV_DSMEM (NSTAGE * STG * 4)  // 66048 bytes

template <int MODE>
__global__ __launch_bounds__(256, 2)
void conv1x1_mma(const float* __restrict__ xin,
                 const float* __restrict__ bias,
                 float* __restrict__ outp) {
    extern __shared__ float S[];

    const int tid  = threadIdx.x;
    const int b    = blockIdx.z;
    const int p0   = blockIdx.x * 256;
    const int o0   = blockIdx.y * 64;
    const int lane = tid & 31;
    const int warp = tid >> 5;
    const int wm   = warp >> 2;
    const int wn   = warp & 3;
    const int gid  = lane >> 2;
    const int tig  = lane & 3;
    const int m0   = wm * 32;
    const int n0   = wn * 64;

    const float* wsrc = (MODE == 0) ? g_wq : (MODE == 1) ? g_wkv : g_wout;
    const float* src  = (MODE == 2) ? g_att : xin;
    const float* xb   = src + (size_t)b * CDIM * HW;

    const int aoo = tid >> 2;
    const int akg = (tid & 3) * 4;
    const int bkk = tid >> 6;
    const int bp4 = (tid & 63) * 4;

    float4 acc[2][8];
#pragma unroll
    for (int mf = 0; mf < 2; mf++)
#pragma unroll
        for (int nf = 0; nf < 8; nf++) acc[mf][nf] = make_float4(0.f, 0.f, 0.f, 0.f);

    auto fill = [&](int st, int k0) {
        cp16(&S[st * STG + aoo * ALD + akg], &wsrc[(size_t)(o0 + aoo) * CDIM + k0 + akg]);
#pragma unroll
        for (int r = 0; r < 4; r++) {
            int kk = bkk + r * 4;
            cp16(&S[st * STG + ASZ + kk * BLD + bp4],
                 &xb[(size_t)(k0 + kk) * HW + p0 + bp4]);
        }
    };

    fill(0, 0);  asm volatile("cp.async.commit_group;\n");
    fill(1, 16); asm volatile("cp.async.commit_group;\n");

    for (int it = 0; it < NITER; it++) {
        asm volatile("cp.async.wait_group 1;\n");
        __syncthreads();
        if (it + 2 < NITER) fill((it + 2) % 3, (it + 2) * 16);
        asm volatile("cp.async.commit_group;\n");

        const float* A = &S[(it % 3) * STG];
        const float* B = A + ASZ;
#pragma unroll
        for (int ks = 0; ks < 16; ks += 8) {
            unsigned a[2][4];
#pragma unroll
            for (int mf = 0; mf < 2; mf++) {
                int mrow = m0 + mf * 16 + gid;
                a[mf][0] = __float_as_uint(A[mrow * ALD + ks + tig]);
                a[mf][1] = __float_as_uint(A[(mrow + 8) * ALD + ks + tig]);
                a[mf][2] = __float_as_uint(A[mrow * ALD + ks + tig + 4]);
                a[mf][3] = __float_as_uint(A[(mrow + 8) * ALD + ks + tig + 4]);
            }
            unsigned bb[8][2];
#pragma unroll
            for (int nf = 0; nf < 8; nf++) {
                int nc = n0 + nf * 8 + gid;
                if (MODE == 2) {
                    bb[nf][0] = __float_as_uint(B[(ks + tig) * BLD + nc]);
                    bb[nf][1] = __float_as_uint(B[(ks + tig + 4) * BLD + nc]);
                } else {
                    bb[nf][0] = tf32r(B[(ks + tig) * BLD + nc]);
                    bb[nf][1] = tf32r(B[(ks + tig + 4) * BLD + nc]);
                }
            }
#pragma unroll
            for (int mf = 0; mf < 2; mf++)
#pragma unroll
                for (int nf = 0; nf < 8; nf++)
                    mma8(acc[mf][nf], a[mf][0], a[mf][1], a[mf][2], a[mf][3],
                         bb[nf][0], bb[nf][1]);
        }
    }

    // ---- epilogue ----
#pragma unroll
    for (int mf = 0; mf < 2; mf++) {
        const int o   = o0 + m0 + mf * 16 + gid;
        const float bo0 = bias[o];
        const float bo8 = bias[o + 8];
        if (MODE == 2) {
#pragma unroll
            for (int nf = 0; nf < 8; nf++) {
                int p = p0 + n0 + nf * 8 + 2 * tig;
                float2 v0 = make_float2(acc[mf][nf].x + bo0, acc[mf][nf].y + bo0);
                float2 v8 = make_float2(acc[mf][nf].z + bo8, acc[mf][nf].w + bo8);
                *(float2*)&outp[((size_t)b * CDIM + o) * HW + p]     = v0;
                *(float2*)&outp[((size_t)b * CDIM + o + 8) * HW + p] = v8;
            }
        } else {
            const int head = (MODE == 0) ? (o >> 5)
                           : ((o < CDIM) ? (o >> 5) : ((o - CDIM) >> 5));
            const int c0ch = (MODE == 0) ? (o & 31)
                           : ((o < CDIM) ? (o & 31) : ((o - CDIM) & 31));
            float* g = (MODE == 0) ? g_q : ((o < CDIM) ? g_k : g_v);
            const bool isq = (MODE == 0);
#pragma unroll
            for (int nf = 0; nf < 8; nf++) {
                int p = p0 + n0 + nf * 8 + 2 * tig;
                int y = p / WWd;
                int x = p - y * WWd;
                int win = b * WIN_PER_B + (y >> 4) * WDIV + (x >> 4);
                int n   = ((y & 15) << 4) + (x & 15);
                size_t base = (((size_t)win * NHEADS + head) * NTOK + n) * HD + c0ch;
                if (isq) {   // fold softmax scale into stored Q, pre-round
                    g[base]      = rnd((acc[mf][nf].x + bo0) * SCALE);
                    g[base + 32] = rnd((acc[mf][nf].y + bo0) * SCALE);
                    g[base + 8]  = rnd((acc[mf][nf].z + bo8) * SCALE);
                    g[base + 40] = rnd((acc[mf][nf].w + bo8) * SCALE);
                } else {
                    g[base]      = rnd(acc[mf][nf].x + bo0);
                    g[base + 32] = rnd(acc[mf][nf].y + bo0);
                    g[base + 8]  = rnd(acc[mf][nf].z + bo8);
                    g[base + 40] = rnd(acc[mf][nf].w + bo8);
                }
            }
        }
    }
}

// ---------------------------------------------------------------------------
// TF32 tensor-core windowed attention (R7/R10 structure). Q/K/V arrive
// tf32-pre-rounded -> bit-direct operands, no cvt on loads/staging.
// P keeps cvt (exp output). g_att stored pre-rounded for conv<2>.
// ---------------------------------------------------------------------------
#define KLD 36
#define VLD 40
#define OLD 33

__global__ __launch_bounds__(256)
void attn_mma(const float* __restrict__ rpb) {
    __shared__ float sm[NTOK * OLD];
    unsigned* kshu = (unsigned*)sm;
    unsigned* vshu = (unsigned*)sm + 32 * KLD;
    float* bsh = sm + 32 * KLD + 32 * VLD;
    float* osh = sm;

    const int tid  = threadIdx.x;
    const int lane = tid & 31;
    const int warp = tid >> 5;
    const int gid  = lane >> 2;
    const int tig  = lane & 3;
    const int m0   = warp * 32;

    const int win  = blockIdx.x / NHEADS;
    const int head = blockIdx.x % NHEADS;
    const size_t whbase = ((size_t)win * NHEADS + head) * NTOK;

    for (int i = tid; i < RPE; i += 256) bsh[i] = rpb[head * RPE + i];

    // Q fragments: pre-rounded (SCALE folded at conv store) -> raw bits
    unsigned qa[2][4][4];
#pragma unroll
    for (int mf = 0; mf < 2; mf++) {
        const float* q0 = g_q + (whbase + m0 + mf * 16 + gid) * HD;
        const float* q1 = q0 + 8 * HD;
#pragma unroll
        for (int ks = 0; ks < 4; ks++) {
            qa[mf][ks][0] = __float_as_uint(q0[ks * 8 + tig]);
            qa[mf][ks][1] = __float_as_uint(q1[ks * 8 + tig]);
            qa[mf][ks][2] = __float_as_uint(q0[ks * 8 + tig + 4]);
            qa[mf][ks][3] = __float_as_uint(q1[ks * 8 + tig + 4]);
        }
    }

    float4 oacc[2][4];
#pragma unroll
    for (int mf = 0; mf < 2; mf++)
#pragma unroll
        for (int nf = 0; nf < 4; nf++) oacc[mf][nf] = make_float4(0.f, 0.f, 0.f, 0.f);
    float lsum[2][2] = {{0.f, 0.f}, {0.f, 0.f}};

    int ro[2][2];
#pragma unroll
    for (int mf = 0; mf < 2; mf++)
#pragma unroll
        for (int rr = 0; rr < 2; rr++) {
            int r = m0 + mf * 16 + gid + rr * 8;
            ro[mf][rr] = (15 - (r >> 4)) * 31 + (15 - (r & 15));
        }

    const int srow = tid >> 3;
    const int scol = (tid & 7) * 4;

    for (int c0 = 0; c0 < NTOK; c0 += 32) {
        __syncthreads();
        {   // stage K, V (already tf32 values: plain bit copy)
            uint4 ku = *(const uint4*)(g_k + (whbase + c0 + srow) * HD + scol);
            *(uint4*)(kshu + srow * KLD + scol) = ku;
            uint4 vu = *(const uint4*)(g_v + (whbase + c0 + srow) * HD + scol);
            *(uint4*)(vshu + srow * VLD + scol) = vu;
        }
        __syncthreads();

        float4 sacc[2][4];
#pragma unroll
        for (int mf = 0; mf < 2; mf++)
#pragma unroll
            for (int nf = 0; nf < 4; nf++) sacc[mf][nf] = make_float4(0.f, 0.f, 0.f, 0.f);
#pragma unroll
        for (int ks = 0; ks < 4; ks++)
#pragma unroll
            for (int nf = 0; nf < 4; nf++) {
                unsigned b0 = kshu[(nf * 8 + gid) * KLD + ks * 8 + tig];
                unsigned b1 = kshu[(nf * 8 + gid) * KLD + ks * 8 + tig + 4];
                mma8(sacc[0][nf], qa[0][ks][0], qa[0][ks][1], qa[0][ks][2], qa[0][ks][3], b0, b1);
                mma8(sacc[1][nf], qa[1][ks][0], qa[1][ks][1], qa[1][ks][2], qa[1][ks][3], b0, b1);
            }

#pragma unroll
        for (int mf = 0; mf < 2; mf++)
#pragma unroll
            for (int nf = 0; nf < 4; nf++) {
                int c  = c0 + nf * 8 + 2 * tig;
                int co = (c >> 4) * 31 + (c & 15);
                float4 s = sacc[mf][nf];
                float px = __expf(s.x + bsh[ro[mf][0] + co]);
                float py = __expf(s.y + bsh[ro[mf][0] + co + 1]);
                float pz = __expf(s.z + bsh[ro[mf][1] + co]);
                float pw = __expf(s.w + bsh[ro[mf][1] + co + 1]);
                lsum[mf][0] += px + py;
                lsum[mf][1] += pz + pw;
                sacc[mf][nf] = make_float4(px, py, pz, pw);
            }

#pragma unroll
        for (int mf = 0; mf < 2; mf++)
#pragma unroll
            for (int ks = 0; ks < 4; ks++) {
                float4 f = sacc[mf][ks];
                int s0 = (lane & 28) | (tig >> 1);
                float x0 = __shfl_sync(0xffffffffu, f.x, s0);
                float y0 = __shfl_sync(0xffffffffu, f.y, s0);
                float z0 = __shfl_sync(0xffffffffu, f.z, s0);
                float w0 = __shfl_sync(0xffffffffu, f.w, s0);
                float x1 = __shfl_sync(0xffffffffu, f.x, s0 + 2);
                float y1 = __shfl_sync(0xffffffffu, f.y, s0 + 2);
                float z1 = __shfl_sync(0xffffffffu, f.z, s0 + 2);
                float w1 = __shfl_sync(0xffffffffu, f.w, s0 + 2);
                bool odd = (tig & 1);
                unsigned a0 = tf32r(odd ? y0 : x0);
                unsigned a1 = tf32r(odd ? w0 : z0);
                unsigned a2 = tf32r(odd ? y1 : x1);
                unsigned a3 = tf32r(odd ? w1 : z1);
#pragma unroll
                for (int nf = 0; nf < 4; nf++) {
                    unsigned b0 = vshu[(ks * 8 + tig) * VLD + nf * 8 + gid];
                    unsigned b1 = vshu[(ks * 8 + tig + 4) * VLD + nf * 8 + gid];
                    mma8(oacc[mf][nf], a0, a1, a2, a3, b0, b1);
                }
            }
    }

    float linv[2][2];
#pragma unroll
    for (int mf = 0; mf < 2; mf++)
#pragma unroll
        for (int rr = 0; rr < 2; rr++) {
            float l = lsum[mf][rr];
            l += __shfl_xor_sync(0xffffffffu, l, 1);
            l += __shfl_xor_sync(0xffffffffu, l, 2);
            linv[mf][rr] = 1.0f / l;
        }

    __syncthreads();
#pragma unroll
    for (int mf = 0; mf < 2; mf++)
#pragma unroll
        for (int nf = 0; nf < 4; nf++) {
            float4 o = oacc[mf][nf];
            int r0 = m0 + mf * 16 + gid;
            int d  = nf * 8 + 2 * tig;
            osh[r0 * OLD + d]           = rnd(o.x * linv[mf][0]);  // pre-round for conv<2>
            osh[r0 * OLD + d + 1]       = rnd(o.y * linv[mf][0]);
            osh[(r0 + 8) * OLD + d]     = rnd(o.z * linv[mf][1]);
            osh[(r0 + 8) * OLD + d + 1] = rnd(o.w * linv[mf][1]);
        }
    __syncthreads();

    const int b    = win / WIN_PER_B;
    const int wrem = win % WIN_PER_B;
    const int py   = (wrem / WDIV) * WS + (tid >> 4);
    const int px   = (wrem % WDIV) * WS + (tid & 15);
    float* gbase = g_att + ((size_t)b * CDIM + head * HD) * HW + (size_t)py * WWd + px;
#pragma unroll
    for (int d = 0; d < HD; d++)
        gbase[(size_t)d * HW] = osh[tid * OLD + d];
}

// ---------------------------------------------------------------------------
extern "C" void kernel_launch(void* const* d_in, const int* in_sizes, int n_in,
                              void* d_out, int out_size) {
    const float* x     = (const float*)d_in[0];
    const float* ref   = (const float*)d_in[1];
    const float* w_q   = (const float*)d_in[2];
    const float* b_q   = (const float*)d_in[3];
    const float* w_kv  = (const float*)d_in[4];
    const float* b_kv  = (const float*)d_in[5];
    const float* w_out = (const float*)d_in[6];
    const float* b_out = (const float*)d_in[7];
    const float* rpb   = (const float*)d_in[8];
    float* out = (float*)d_out;

    cudaFuncSetAttribute(conv1x1_mma<0>, cudaFuncAttributeMaxDynamicSharedMemorySize, CONV_DSMEM);
    cudaFuncSetAttribute(conv1x1_mma<1>, cudaFuncAttributeMaxDynamicSharedMemorySize, CONV_DSMEM);
    cudaFuncSetAttribute(conv1x1_mma<2>, cudaFuncAttributeMaxDynamicSharedMemorySize, CONV_DSMEM);

    dim3 blk(256);
    round_weights<<<(2 * CDIM * CDIM + 255) / 256, blk>>>(w_q, w_kv, w_out);
    conv1x1_mma<0><<<dim3(HW / 256, CDIM / 64, BATCH), blk, CONV_DSMEM>>>(x, b_q, nullptr);
    conv1x1_mma<1><<<dim3(HW / 256, (2 * CDIM) / 64, BATCH), blk, CONV_DSMEM>>>(ref, b_kv, nullptr);
    attn_mma<<<NWIN * NHEADS, blk>>>(rpb);
    conv1x1_mma<2><<<dim3(HW / 256, CDIM / 64, BATCH), blk, CONV_DSMEM>>>(nullptr, b_out, out);
}